// round 2
// baseline (speedup 1.0000x reference)
#include <cuda_runtime.h>

// Problem constants
#define BB    64
#define CDIM  128
#define HW    32
#define NPX   1024            // 32*32
#define WDIM  147584          // 128*128*9 + 128
#define WOFF  147456          // 128*128*9

// Scratch: projected cnn_inp, (B, 128, 32, 32) fp32 = 33.5 MB
__device__ float g_inp[(size_t)BB * CDIM * NPX];

// ---------------------------------------------------------------------------
// Kernel 1: projection GEMM per sample
//   g_inp[b,o,p] = sum_{c=0..255} cat[b,c,p] * proj_w[o,c] + proj_b[o]
//   cat = [lhs ; rhs] along channels.
// Block tile: 64 o x 128 px. Thread tile: 4 o x 8 px. 256 threads.
// Grid: (px_tiles=8, o_tiles=2, B=64)
// ---------------------------------------------------------------------------
__global__ __launch_bounds__(256) void proj_kernel(
    const float* __restrict__ lhs, const float* __restrict__ rhs,
    const float* __restrict__ pw,  const float* __restrict__ pb)
{
    const int b      = blockIdx.z;
    const int obase  = blockIdx.y * 64;
    const int pxbase = blockIdx.x * 128;
    const int tid    = threadIdx.x;
    const int px0    = (tid & 15) * 8;
    const int o0     = (tid >> 4) * 4;

    __shared__ float As[32][128];   // [c_chunk][px]
    __shared__ float Bs[32][65];    // [c_chunk][o]  (pad 65: conflict-free transpose)

    float acc[4][8];
    #pragma unroll
    for (int i = 0; i < 4; i++) {
        float bias = pb[obase + o0 + i];
        #pragma unroll
        for (int j = 0; j < 8; j++) acc[i][j] = bias;
    }

    for (int cb = 0; cb < 256; cb += 32) {
        // ---- load activation tile: 32c x 128px, float4, coalesced
        #pragma unroll
        for (int v = 0; v < 4; v++) {
            int lin = tid + v * 256;       // float4 index, 0..1023
            int c   = lin >> 5;
            int p4  = lin & 31;
            int cc  = cb + c;
            const float* src = (cc < CDIM)
                ? (lhs + ((size_t)b * CDIM + cc) * NPX)
                : (rhs + ((size_t)b * CDIM + (cc - CDIM)) * NPX);
            float4 val = *reinterpret_cast<const float4*>(src + pxbase + p4 * 4);
            *reinterpret_cast<float4*>(&As[c][p4 * 4]) = val;
        }
        // ---- load weight tile 64o x 32c (transposed into smem, padded rows)
        #pragma unroll
        for (int v = 0; v < 8; v++) {
            int lin = tid + v * 256;       // 0..2047
            int o   = lin >> 5;
            int c   = lin & 31;
            Bs[c][o] = pw[(obase + o) * 256 + cb + c];
        }
        __syncthreads();

        #pragma unroll
        for (int c = 0; c < 32; c++) {
            float a[8], w[4];
            #pragma unroll
            for (int j = 0; j < 8; j++) a[j] = As[c][px0 + j];
            #pragma unroll
            for (int i = 0; i < 4; i++) w[i] = Bs[c][o0 + i];
            #pragma unroll
            for (int i = 0; i < 4; i++)
                #pragma unroll
                for (int j = 0; j < 8; j++)
                    acc[i][j] += a[j] * w[i];
        }
        __syncthreads();
    }

    #pragma unroll
    for (int i = 0; i < 4; i++) {
        float* dst = g_inp + ((size_t)b * CDIM + obase + o0 + i) * NPX + pxbase + px0;
        #pragma unroll
        for (int j = 0; j < 8; j += 4)
            *reinterpret_cast<float4*>(dst + j) =
                make_float4(acc[i][j], acc[i][j+1], acc[i][j+2], acc[i][j+3]);
    }
}

// ---------------------------------------------------------------------------
// Kernel 2: per-sample 3x3 conv (pad 1), weights & bias from question_rep.
//   out[b,o,y,x] = bias[b,o] + sum_{c,ky,kx} g_inp[b,c,y+ky-1,x+kx-1]
//                                           * qrep[b, (o*128+c)*9 + ky*3+kx]
// Block: (b, 4-row spatial tile) x all 128 o. 256 threads.
// Thread tile: 8 o x 8 px (one row, 8 consecutive cols).
// c processed in chunks of 8.
// Grid: (row_tiles=8, B=64)
// ---------------------------------------------------------------------------
#define CC 8

__global__ __launch_bounds__(256, 2) void conv_kernel(
    const float* __restrict__ qrep, float* __restrict__ out)
{
    const int rowtile = blockIdx.x;          // 0..7  (4 output rows each)
    const int b       = blockIdx.y;
    const int tid     = threadIdx.x;
    const int og      = tid >> 4;            // 0..15 -> outputs og*8 .. og*8+7
    const int pxg     = tid & 15;
    const int r       = pxg >> 2;            // row within tile, 0..3
    const int cg      = pxg & 3;             // col group (8 cols each)
    const int rowbase = rowtile * 4;

    __shared__ float Is[CC][6][38];          // input tile + halo, padded cols
    __shared__ float Ws[CDIM][72];           // [o][c_in_chunk*9 + tap]

    const float* wsrc = qrep + (size_t)b * WDIM;

    float acc[8][8];
    #pragma unroll
    for (int i = 0; i < 8; i++)
        #pragma unroll
        for (int j = 0; j < 8; j++) acc[i][j] = 0.f;

    for (int cbase = 0; cbase < CDIM; cbase += CC) {
        // ---- load input tile: CC channels x 6 rows x 34 cols (halo, zero-pad)
        for (int i = tid; i < CC * 6 * 34; i += 256) {
            int c    = i / 204;
            int rem  = i - c * 204;
            int rr   = rem / 34;
            int col  = rem - rr * 34;
            int grow = rowbase + rr - 1;
            int gcol = col - 1;
            float v = 0.f;
            if ((unsigned)grow < 32u && (unsigned)gcol < 32u)
                v = g_inp[((size_t)b * CDIM + cbase + c) * NPX + grow * 32 + gcol];
            Is[c][rr][col] = v;
        }
        // ---- load weight chunk: 128 o x (CC*9). Contiguous LDG per o,
        //      contiguous STS (conflict-free).
        #pragma unroll
        for (int v = 0; v < (CDIM * 72) / 256; v++) {
            int i = tid + v * 256;
            int o = i / 72;
            int j = i - o * 72;
            Ws[o][j] = wsrc[(o * CDIM + cbase) * 9 + j];
        }
        __syncthreads();

        #pragma unroll
        for (int ci = 0; ci < CC; ci++) {
            // stage this thread's input window into registers: 3 rows x 10 cols
            float inr[3][10];
            #pragma unroll
            for (int ky = 0; ky < 3; ky++)
                #pragma unroll
                for (int t = 0; t < 10; t++)
                    inr[ky][t] = Is[ci][r + ky][cg * 8 + t];

            #pragma unroll
            for (int ky = 0; ky < 3; ky++)
                #pragma unroll
                for (int kx = 0; kx < 3; kx++)
                    #pragma unroll
                    for (int oi = 0; oi < 8; oi++) {
                        float w = Ws[og * 8 + oi][ci * 9 + ky * 3 + kx];
                        #pragma unroll
                        for (int px = 0; px < 8; px++)
                            acc[oi][px] += w * inr[ky][kx + px];
                    }
        }
        __syncthreads();
    }

    // ---- epilogue: add per-sample bias, store
    const int orow = rowbase + r;
    #pragma unroll
    for (int oi = 0; oi < 8; oi++) {
        int   o    = og * 8 + oi;
        float bias = qrep[(size_t)b * WDIM + WOFF + o];
        float* dst = out + ((size_t)b * CDIM + o) * NPX + orow * 32 + cg * 8;
        #pragma unroll
        for (int px = 0; px < 8; px += 4)
            *reinterpret_cast<float4*>(dst + px) =
                make_float4(acc[oi][px]   + bias, acc[oi][px+1] + bias,
                            acc[oi][px+2] + bias, acc[oi][px+3] + bias);
    }
}

// ---------------------------------------------------------------------------
extern "C" void kernel_launch(void* const* d_in, const int* in_sizes, int n_in,
                              void* d_out, int out_size)
{
    const float* qrep = (const float*)d_in[0];   // (64, 147584)
    const float* lhs  = (const float*)d_in[1];   // (64, 128, 32, 32)
    const float* rhs  = (const float*)d_in[2];   // (64, 128, 32, 32)
    const float* pw   = (const float*)d_in[3];   // (128, 256)
    const float* pb   = (const float*)d_in[4];   // (128,)
    float* out = (float*)d_out;                  // (64, 128, 32, 32)

    dim3 pgrid(NPX / 128, CDIM / 64, BB);        // (8, 2, 64)
    proj_kernel<<<pgrid, 256>>>(lhs, rhs, pw, pb);

    dim3 cgrid(HW / 4, BB);                      // (8, 64)
    conv_kernel<<<cgrid, 256>>>(qrep, out);
}

// round 4
// speedup vs baseline: 3.0742x; 3.0742x over previous
#include <cuda_runtime.h>
#include <cstdint>

// Problem constants
#define BB    64
#define CDIM  128
#define NPX   1024
#define WDIM  147584          // 128*128*9 + 128
#define WOFF  147456

// ---------------------------------------------------------------------------
// Device scratch (__device__ globals: sanctioned alloc-free workaround)
// g_cat: tf32-rounded concat input      [b][c=256][px=1024]
// pw_t : tf32-rounded proj weights      [o=128][c=256]
// w_t  : tf32-rounded conv weights      [b][tap=9][o=128][c=128]
// g_pad: tf32-rounded projected input   [b][y=34][x=32][c=128]  (y pads = 0)
// ---------------------------------------------------------------------------
__device__ float g_cat[(size_t)BB * 256 * NPX];
__device__ float pw_t [CDIM * 256];
__device__ float w_t  [(size_t)BB * 9 * CDIM * CDIM];
__device__ float g_pad[(size_t)BB * 34 * 32 * CDIM];

// ===========================================================================
// helpers
// ===========================================================================
__device__ __forceinline__ uint32_t smem_u32(const void* p) {
    uint32_t a;
    asm("{ .reg .u64 t; cvta.to.shared.u64 t, %1; cvt.u32.u64 %0, t; }"
        : "=r"(a) : "l"(p));
    return a;
}
__device__ __forceinline__ float rna_tf32(float x) {
    uint32_t r;
    asm("cvt.rna.tf32.f32 %0, %1;" : "=r"(r) : "f"(x));
    return __uint_as_float(r);
}

#define CP_ASYNC16(dst_u32, src_ptr, szr) \
    asm volatile("cp.async.cg.shared.global [%0], [%1], 16, %2;" \
                 :: "r"(dst_u32), "l"(src_ptr), "r"(szr) : "memory")
#define CP_COMMIT() asm volatile("cp.async.commit_group;" ::: "memory")
#define CP_WAIT(N)  asm volatile("cp.async.wait_group %0;" :: "n"(N) : "memory")

// m16n8k8 tf32 MMA (fragments: see PTX ISA; operands pre-rounded to tf32)
__device__ __forceinline__ void mma_tf32(float* d, const float* a,
                                         float b0, float b1) {
    asm volatile(
        "mma.sync.aligned.m16n8k8.row.col.f32.tf32.tf32.f32 "
        "{%0,%1,%2,%3}, {%4,%5,%6,%7}, {%8,%9}, {%0,%1,%2,%3};"
        : "+f"(d[0]), "+f"(d[1]), "+f"(d[2]), "+f"(d[3])
        : "r"(__float_as_uint(a[0])), "r"(__float_as_uint(a[1])),
          "r"(__float_as_uint(a[2])), "r"(__float_as_uint(a[3])),
          "r"(__float_as_uint(b0)),   "r"(__float_as_uint(b1)));
}

// ===========================================================================
// Kernel 0a: elementwise tf32 rounding of cat and pw
// ===========================================================================
#define CAT_F4 ((size_t)BB * 256 * NPX / 4)   // 4,194,304
#define PW_F4  (CDIM * 256 / 4)               // 8,192
__global__ __launch_bounds__(256) void round_kernel(
    const float* __restrict__ lhs, const float* __restrict__ rhs,
    const float* __restrict__ pw)
{
    size_t i = (size_t)blockIdx.x * 256 + threadIdx.x;
    if (i < CAT_F4) {
        size_t j   = i * 4;                   // flat float index in g_cat
        size_t b   = j >> 18;                 // / (256*1024)
        size_t rem = j & 0x3FFFF;
        int    c   = (int)(rem >> 10);
        int    px  = (int)(rem & 1023);
        const float* src = (c < CDIM)
            ? (lhs + ((b * CDIM + c) * NPX + px))
            : (rhs + ((b * CDIM + (c - CDIM)) * NPX + px));
        float4 v = *reinterpret_cast<const float4*>(src);
        v.x = rna_tf32(v.x); v.y = rna_tf32(v.y);
        v.z = rna_tf32(v.z); v.w = rna_tf32(v.w);
        *reinterpret_cast<float4*>(g_cat + j) = v;
    } else if (i - CAT_F4 < PW_F4) {
        size_t j = (i - CAT_F4) * 4;
        float4 v = *reinterpret_cast<const float4*>(pw + j);
        v.x = rna_tf32(v.x); v.y = rna_tf32(v.y);
        v.z = rna_tf32(v.z); v.w = rna_tf32(v.w);
        *reinterpret_cast<float4*>(pw_t + j) = v;
    }
}

// ===========================================================================
// Kernel 0b: conv-weight transpose + tf32 rounding
//   w_t[b][tap][o][c] = rna(qrep[b, o*1152 + c*9 + tap])
// ===========================================================================
__global__ __launch_bounds__(128) void wtrans_kernel(const float* __restrict__ qrep)
{
    const int o = blockIdx.x, b = blockIdx.y;
    __shared__ float s[1152];
    const float* src = qrep + (size_t)b * WDIM + o * 1152;
    for (int i = threadIdx.x; i < 1152; i += 128) s[i] = src[i];
    __syncthreads();
    const int c = threadIdx.x;
    #pragma unroll
    for (int tap = 0; tap < 9; tap++)
        w_t[(((size_t)b * 9 + tap) * CDIM + o) * CDIM + c] = rna_tf32(s[c * 9 + tap]);
}

// ===========================================================================
// Kernel 1: projection via mma.sync tf32
//   g_pad[b][1+y][x][o] = rna( sum_c pw[o,c]*cat[b,c,(y,x)] + pb[o] )
// CTA: 128 o x 128 px, 8 warps (2 o-blocks x 4 px-blocks), warp 64x32.
// K = 256, 8 double-buffered cp.async stages of 32.
// ===========================================================================
#define AST 36          // A smem stride (floats)
#define PBST 136        // proj B smem stride
#define PROJ_STAGE (128*AST + 32*PBST)      // 8960 floats
#define PROJ_SMEM  (2*PROJ_STAGE*4)         // 71680 B

__global__ __launch_bounds__(256) void proj_kernel(
    const float* __restrict__ pb)
{
    extern __shared__ float sm[];
    const int tid = threadIdx.x, lane = tid & 31, warp = tid >> 5;
    const int g = lane >> 2, q = lane & 3;
    const int ow = warp & 1, pwv = warp >> 1;
    const int b = blockIdx.y, pxbase = blockIdx.x * 128;

    float* bufA[2] = { sm,              sm + PROJ_STAGE };
    float* bufB[2] = { sm + 128 * AST,  sm + PROJ_STAGE + 128 * AST };

    auto issue = [&](int s) {
        const int cb = s * 32, buf = s & 1;
        const uint32_t sa = smem_u32(bufA[buf]);
        const uint32_t sb = smem_u32(bufB[buf]);
        #pragma unroll
        for (int i = 0; i < 4; i++) {           // A: 128 rows x 32 k
            int f = tid + i * 256;              // float4 idx 0..1023
            int r = f >> 3, k4 = f & 7;
            const float* src = pw_t + r * 256 + cb + k4 * 4;
            CP_ASYNC16(sa + (r * AST + k4 * 4) * 4, src, 16);
        }
        #pragma unroll
        for (int i = 0; i < 4; i++) {           // B: 32 k x 128 px
            int f = tid + i * 256;
            int kr = f >> 5, n4 = f & 31;
            const float* src = g_cat + ((size_t)b * 256 + cb + kr) * NPX
                                     + pxbase + n4 * 4;
            CP_ASYNC16(sb + (kr * PBST + n4 * 4) * 4, src, 16);
        }
        CP_COMMIT();
    };

    float acc[4][4][4];
    #pragma unroll
    for (int mt = 0; mt < 4; mt++)
        #pragma unroll
        for (int nt = 0; nt < 4; nt++)
            #pragma unroll
            for (int k = 0; k < 4; k++) acc[mt][nt][k] = 0.f;

    issue(0);
    for (int s = 0; s < 8; s++) {
        if (s + 1 < 8) { issue(s + 1); CP_WAIT(1); }
        else           { CP_WAIT(0); }
        __syncthreads();
        const float* A  = bufA[s & 1];
        const float* Bm = bufB[s & 1];
        #pragma unroll
        for (int j = 0; j < 4; j++) {
            float ar[4][4];
            #pragma unroll
            for (int mt = 0; mt < 4; mt++) {
                const float* ap = A + (ow * 64 + mt * 16 + g) * AST + j * 8 + q;
                ar[mt][0] = ap[0];        ar[mt][1] = ap[8 * AST];
                ar[mt][2] = ap[4];        ar[mt][3] = ap[8 * AST + 4];
            }
            #pragma unroll
            for (int nt = 0; nt < 4; nt++) {
                const float* bp = Bm + (j * 8 + q) * PBST + pwv * 32 + nt * 8 + g;
                float b0 = bp[0], b1 = bp[4 * PBST];
                #pragma unroll
                for (int mt = 0; mt < 4; mt++)
                    mma_tf32(acc[mt][nt], ar[mt], b0, b1);
            }
        }
        __syncthreads();
    }

    // Epilogue: +bias, rna, transpose through smem, coalesced store to g_pad
    float* T = sm;                               // [128 px][132]
    #pragma unroll
    for (int mt = 0; mt < 4; mt++) {
        int o = ow * 64 + mt * 16 + g;
        float bl = __ldg(pb + o), bh = __ldg(pb + o + 8);
        #pragma unroll
        for (int nt = 0; nt < 4; nt++) {
            int n0 = pwv * 32 + nt * 8 + 2 * q;
            T[n0 * 132 + o]           = rna_tf32(acc[mt][nt][0] + bl);
            T[(n0 + 1) * 132 + o]     = rna_tf32(acc[mt][nt][1] + bl);
            T[n0 * 132 + o + 8]       = rna_tf32(acc[mt][nt][2] + bh);
            T[(n0 + 1) * 132 + o + 8] = rna_tf32(acc[mt][nt][3] + bh);
        }
    }
    __syncthreads();
    #pragma unroll
    for (int i = 0; i < 16; i++) {
        int idx = tid + i * 256;                 // 0..4095 float4 slots
        int row = idx >> 5, c4 = idx & 31;
        int px = pxbase + row, y = px >> 5, x = px & 31;
        float4 v = *reinterpret_cast<const float4*>(T + row * 132 + c4 * 4);
        *reinterpret_cast<float4*>(
            g_pad + (((size_t)b * 34 + 1 + y) * 32 + x) * CDIM + c4 * 4) = v;
    }
}

// ===========================================================================
// Kernel 2: per-sample 3x3 conv as shifted-tap implicit GEMM (mma.sync tf32)
//   out[b,o,px] = bias + sum_{tap,c} w_t[b,tap,o,c] * g_pad[b, y+dy, x+dx-1, c]
// CTA: (4-row px tile, sample): 128 o x 128 px, K = 9 taps x 128.
// 36 double-buffered cp.async stages of 32 k.
// ===========================================================================
#define CONV_STAGE (2*128*AST)                  // A + B, 9216 floats
#define CONV_SMEM  (2*CONV_STAGE*4)             // 73728 B

__global__ __launch_bounds__(256) void conv_kernel(
    const float* __restrict__ qrep, float* __restrict__ out)
{
    extern __shared__ float sm[];
    const int tid = threadIdx.x, lane = tid & 31, warp = tid >> 5;
    const int g = lane >> 2, q = lane & 3;
    const int ow = warp & 1, pwv = warp >> 1;
    const int ytile = blockIdx.x, b = blockIdx.y;

    float* bufA[2] = { sm,             sm + CONV_STAGE };
    float* bufB[2] = { sm + 128 * AST, sm + CONV_STAGE + 128 * AST };

    auto issue = [&](int s) {
        const int tap = s >> 2, kc = s & 3, buf = s & 1;
        const int dy = tap / 3, dx = tap % 3;
        const uint32_t sa = smem_u32(bufA[buf]);
        const uint32_t sb = smem_u32(bufB[buf]);
        const float* wsrc = w_t + ((size_t)b * 9 + tap) * (CDIM * CDIM);
        #pragma unroll
        for (int i = 0; i < 4; i++) {           // A: 128 o x 32 k
            int f = tid + i * 256;
            int r = f >> 3, k4 = f & 7;
            CP_ASYNC16(sa + (r * AST + k4 * 4) * 4,
                       wsrc + r * CDIM + kc * 32 + k4 * 4, 16);
        }
        #pragma unroll
        for (int i = 0; i < 4; i++) {           // B: 128 px x 32 k (shifted)
            int f = tid + i * 256;
            int r = f >> 3, k4 = f & 7;
            int x = r & 31, rr = r >> 5;
            int xin = x + dx - 1;
            int ok  = ((unsigned)xin < 32u) ? 16 : 0;
            int xc  = xin < 0 ? 0 : (xin > 31 ? 31 : xin);
            int row = ytile * 4 + dy + rr;
            const float* src = g_pad + (((size_t)b * 34 + row) * 32 + xc) * CDIM
                                     + kc * 32 + k4 * 4;
            CP_ASYNC16(sb + (r * AST + k4 * 4) * 4, src, ok);
        }
        CP_COMMIT();
    };

    float acc[4][4][4];
    #pragma unroll
    for (int mt = 0; mt < 4; mt++)
        #pragma unroll
        for (int nt = 0; nt < 4; nt++)
            #pragma unroll
            for (int k = 0; k < 4; k++) acc[mt][nt][k] = 0.f;

    issue(0);
    for (int s = 0; s < 36; s++) {
        if (s + 1 < 36) { issue(s + 1); CP_WAIT(1); }
        else            { CP_WAIT(0); }
        __syncthreads();
        const float* A  = bufA[s & 1];
        const float* Bm = bufB[s & 1];
        #pragma unroll
        for (int j = 0; j < 4; j++) {
            float ar[4][4];
            #pragma unroll
            for (int mt = 0; mt < 4; mt++) {
                const float* ap = A + (ow * 64 + mt * 16 + g) * AST + j * 8 + q;
                ar[mt][0] = ap[0];        ar[mt][1] = ap[8 * AST];
                ar[mt][2] = ap[4];        ar[mt][3] = ap[8 * AST + 4];
            }
            #pragma unroll
            for (int nt = 0; nt < 4; nt++) {
                const float* bp = Bm + (pwv * 32 + nt * 8 + g) * AST + j * 8 + q;
                float b0 = bp[0], b1 = bp[4];
                #pragma unroll
                for (int mt = 0; mt < 4; mt++)
                    mma_tf32(acc[mt][nt], ar[mt], b0, b1);
            }
        }
        __syncthreads();
    }

    // Epilogue: +per-sample bias, direct float2 stores (px pairs contiguous)
    const float* bsrc = qrep + (size_t)b * WDIM + WOFF;
    #pragma unroll
    for (int mt = 0; mt < 4; mt++) {
        int o  = ow * 64 + mt * 16 + g;
        float bl = __ldg(bsrc + o), bh = __ldg(bsrc + o + 8);
        #pragma unroll
        for (int nt = 0; nt < 4; nt++) {
            int px = ytile * 128 + pwv * 32 + nt * 8 + 2 * q;
            float2 v0 = make_float2(acc[mt][nt][0] + bl, acc[mt][nt][1] + bl);
            float2 v1 = make_float2(acc[mt][nt][2] + bh, acc[mt][nt][3] + bh);
            *reinterpret_cast<float2*>(out + ((size_t)b * CDIM + o)     * NPX + px) = v0;
            *reinterpret_cast<float2*>(out + ((size_t)b * CDIM + o + 8) * NPX + px) = v1;
        }
    }
}

// ===========================================================================
extern "C" void kernel_launch(void* const* d_in, const int* in_sizes, int n_in,
                              void* d_out, int out_size)
{
    const float* qrep = (const float*)d_in[0];   // (64, 147584)
    const float* lhs  = (const float*)d_in[1];   // (64, 128, 32, 32)
    const float* rhs  = (const float*)d_in[2];   // (64, 128, 32, 32)
    const float* pw   = (const float*)d_in[3];   // (128, 256)
    const float* pb   = (const float*)d_in[4];   // (128,)
    float* out = (float*)d_out;                  // (64, 128, 32, 32)

    static bool attr_done = false;
    if (!attr_done) {
        cudaFuncSetAttribute(proj_kernel,
            cudaFuncAttributeMaxDynamicSharedMemorySize, PROJ_SMEM);
        cudaFuncSetAttribute(conv_kernel,
            cudaFuncAttributeMaxDynamicSharedMemorySize, CONV_SMEM);
        attr_done = true;
    }

    size_t nround = CAT_F4 + PW_F4;
    round_kernel<<<(unsigned)((nround + 255) / 256), 256>>>(lhs, rhs, pw);
    wtrans_kernel<<<dim3(CDIM, BB), 128>>>(qrep);
    proj_kernel<<<dim3(8, BB), 256, PROJ_SMEM>>>(pb);
    conv_kernel<<<dim3(8, BB), 256, CONV_SMEM>>>(qrep, out);
}

// round 6
// speedup vs baseline: 3.1533x; 1.0257x over previous
#include <cuda_runtime.h>
#include <cstdint>

// Problem constants
#define BB    64
#define CDIM  128
#define NPX   1024
#define WDIM  147584          // 128*128*9 + 128
#define WOFF  147456

// ---------------------------------------------------------------------------
// Device scratch
// w_t  : tf32-rounded conv weights      [b][tap=9][o=128][c=128]
// g_pad: tf32-rounded projected input   [b][y=34][x=32][c=128]  (y pads = 0)
// ---------------------------------------------------------------------------
__device__ float w_t  [(size_t)BB * 9 * CDIM * CDIM];
__device__ float g_pad[(size_t)BB * 34 * 32 * CDIM];

// ===========================================================================
// helpers
// ===========================================================================
__device__ __forceinline__ uint32_t smem_u32(const void* p) {
    uint32_t a;
    asm("{ .reg .u64 t; cvta.to.shared.u64 t, %1; cvt.u32.u64 %0, t; }"
        : "=r"(a) : "l"(p));
    return a;
}
__device__ __forceinline__ float rna_tf32(float x) {
    uint32_t r;
    asm("cvt.rna.tf32.f32 %0, %1;" : "=r"(r) : "f"(x));
    return __uint_as_float(r);
}

#define CP_ASYNC16(dst_u32, src_ptr) \
    asm volatile("cp.async.cg.shared.global [%0], [%1], 16;" \
                 :: "r"(dst_u32), "l"(src_ptr) : "memory")
#define CP_COMMIT() asm volatile("cp.async.commit_group;" ::: "memory")
#define CP_WAIT(N)  asm volatile("cp.async.wait_group %0;" :: "n"(N) : "memory")

// m16n8k8 tf32 MMA (operands must already be tf32-rounded bit patterns)
__device__ __forceinline__ void mma_tf32(float* d, const float* a,
                                         float b0, float b1) {
    asm volatile(
        "mma.sync.aligned.m16n8k8.row.col.f32.tf32.tf32.f32 "
        "{%0,%1,%2,%3}, {%4,%5,%6,%7}, {%8,%9}, {%0,%1,%2,%3};"
        : "+f"(d[0]), "+f"(d[1]), "+f"(d[2]), "+f"(d[3])
        : "r"(__float_as_uint(a[0])), "r"(__float_as_uint(a[1])),
          "r"(__float_as_uint(a[2])), "r"(__float_as_uint(a[3])),
          "r"(__float_as_uint(b0)),   "r"(__float_as_uint(b1)));
}

// ===========================================================================
// Kernel 0: conv-weight transpose + tf32 rounding
//   w_t[b][tap][o][c] = rna(qrep[b, o*1152 + c*9 + tap])
// ===========================================================================
__global__ __launch_bounds__(128) void wtrans_kernel(const float* __restrict__ qrep)
{
    const int o = blockIdx.x, b = blockIdx.y;
    __shared__ float s[1152];
    const float* src = qrep + (size_t)b * WDIM + o * 1152;
    for (int i = threadIdx.x; i < 1152; i += 128) s[i] = src[i];
    __syncthreads();
    const int c = threadIdx.x;
    #pragma unroll
    for (int tap = 0; tap < 9; tap++)
        w_t[(((size_t)b * 9 + tap) * CDIM + o) * CDIM + c] = rna_tf32(s[c * 9 + tap]);
}

// ===========================================================================
// Kernel 1: projection via mma.sync tf32, rounding applied to register
// fragments (raw lhs/rhs/pw read directly; no pre-rounding pass).
//   g_pad[b][1+y][x][o] = rna( sum_c pw[o,c]*cat[b,c,(y,x)] + pb[o] )
// CTA: 128 o x 128 px, 8 warps (2x4), warp 64x32. K=256, 8 stages of 32.
// ===========================================================================
#define AST 36
#define PBST 136
#define PROJ_STAGE (128*AST + 32*PBST)      // 8960 floats
#define PROJ_SMEM  (2*PROJ_STAGE*4)         // 71680 B

__global__ __launch_bounds__(256) void proj_kernel(
    const float* __restrict__ lhs, const float* __restrict__ rhs,
    const float* __restrict__ pw,  const float* __restrict__ pb)
{
    extern __shared__ float sm[];
    const int tid = threadIdx.x, lane = tid & 31, warp = tid >> 5;
    const int g = lane >> 2, q = lane & 3;
    const int ow = warp & 1, pwv = warp >> 1;
    const int b = blockIdx.y, pxbase = blockIdx.x * 128;

    float* bufA[2] = { sm,              sm + PROJ_STAGE };
    float* bufB[2] = { sm + 128 * AST,  sm + PROJ_STAGE + 128 * AST };

    auto issue = [&](int s) {
        const int cb = s * 32, buf = s & 1;
        const uint32_t sa = smem_u32(bufA[buf]);
        const uint32_t sb = smem_u32(bufB[buf]);
        #pragma unroll
        for (int i = 0; i < 4; i++) {           // A: 128 o x 32 k (raw pw)
            int f = tid + i * 256;
            int r = f >> 3, k4 = f & 7;
            CP_ASYNC16(sa + (r * AST + k4 * 4) * 4, pw + r * 256 + cb + k4 * 4);
        }
        #pragma unroll
        for (int i = 0; i < 4; i++) {           // B: 32 k x 128 px (raw cat)
            int f = tid + i * 256;
            int kr = f >> 5, n4 = f & 31;
            int c  = cb + kr;
            const float* src = (c < CDIM)
                ? (lhs + ((size_t)b * CDIM + c) * NPX + pxbase + n4 * 4)
                : (rhs + ((size_t)b * CDIM + (c - CDIM)) * NPX + pxbase + n4 * 4);
            CP_ASYNC16(sb + (kr * PBST + n4 * 4) * 4, src);
        }
        CP_COMMIT();
    };

    float acc[4][4][4];
    #pragma unroll
    for (int mt = 0; mt < 4; mt++)
        #pragma unroll
        for (int nt = 0; nt < 4; nt++)
            #pragma unroll
            for (int k = 0; k < 4; k++) acc[mt][nt][k] = 0.f;

    issue(0);
    for (int s = 0; s < 8; s++) {
        if (s + 1 < 8) { issue(s + 1); CP_WAIT(1); }
        else           { CP_WAIT(0); }
        __syncthreads();
        const float* A  = bufA[s & 1];
        const float* Bm = bufB[s & 1];
        #pragma unroll
        for (int j = 0; j < 4; j++) {
            float ar[4][4];
            #pragma unroll
            for (int mt = 0; mt < 4; mt++) {
                const float* ap = A + (ow * 64 + mt * 16 + g) * AST + j * 8 + q;
                ar[mt][0] = rna_tf32(ap[0]);
                ar[mt][1] = rna_tf32(ap[8 * AST]);
                ar[mt][2] = rna_tf32(ap[4]);
                ar[mt][3] = rna_tf32(ap[8 * AST + 4]);
            }
            #pragma unroll
            for (int nt = 0; nt < 4; nt++) {
                const float* bp = Bm + (j * 8 + q) * PBST + pwv * 32 + nt * 8 + g;
                float b0 = rna_tf32(bp[0]), b1 = rna_tf32(bp[4 * PBST]);
                #pragma unroll
                for (int mt = 0; mt < 4; mt++)
                    mma_tf32(acc[mt][nt], ar[mt], b0, b1);
            }
        }
        __syncthreads();
    }

    // Epilogue: +bias, rna, transpose through smem, coalesced store to g_pad
    float* T = sm;                               // [128 px][132]
    #pragma unroll
    for (int mt = 0; mt < 4; mt++) {
        int o = ow * 64 + mt * 16 + g;
        float bl = __ldg(pb + o), bh = __ldg(pb + o + 8);
        #pragma unroll
        for (int nt = 0; nt < 4; nt++) {
            int n0 = pwv * 32 + nt * 8 + 2 * q;
            T[n0 * 132 + o]           = rna_tf32(acc[mt][nt][0] + bl);
            T[(n0 + 1) * 132 + o]     = rna_tf32(acc[mt][nt][1] + bl);
            T[n0 * 132 + o + 8]       = rna_tf32(acc[mt][nt][2] + bh);
            T[(n0 + 1) * 132 + o + 8] = rna_tf32(acc[mt][nt][3] + bh);
        }
    }
    __syncthreads();
    #pragma unroll
    for (int i = 0; i < 16; i++) {
        int idx = tid + i * 256;
        int row = idx >> 5, c4 = idx & 31;
        int px = pxbase + row, y = px >> 5, x = px & 31;
        float4 v = *reinterpret_cast<const float4*>(T + row * 132 + c4 * 4);
        *reinterpret_cast<float4*>(
            g_pad + (((size_t)b * 34 + 1 + y) * 32 + x) * CDIM + c4 * 4) = v;
    }
}

// ===========================================================================
// Kernel 2: conv as shifted-tap implicit GEMM, B resident in smem.
// CTA: 128 o x 128 px (4 output rows), 512 threads, 16 warps (4o x 4px),
// warp tile 32o x 32px.
// B: 6 rows x 34 x(x-padded, zeros) x 128 c, loaded ONCE (c-stride 132).
// A: w_t tap slabs streamed in 18 stages of 64k, 3-buffer / 2-deep prefetch.
// ===========================================================================
#define CAST 68                                  // conv A smem stride
#define CBST 132                                 // conv B smem c-stride
#define CONV_ASTG (128 * CAST)                   // 8704 floats per A stage
#define CONV_BSZ  (6 * 34 * CBST)                // 26928 floats
#define CONV_SMEM ((CONV_BSZ + 3 * CONV_ASTG) * 4)   // 212160 B

__global__ __launch_bounds__(512) void conv_kernel(
    const float* __restrict__ qrep, float* __restrict__ out)
{
    extern __shared__ float sm[];
    float* Bs = sm;
    float* Abuf[3] = { sm + CONV_BSZ, sm + CONV_BSZ + CONV_ASTG,
                       sm + CONV_BSZ + 2 * CONV_ASTG };

    const int tid = threadIdx.x, lane = tid & 31, warp = tid >> 5;
    const int g = lane >> 2, q = lane & 3;
    const int pwv = warp & 3, ow = warp >> 2;
    const int ytile = blockIdx.x, b = blockIdx.y;

    // ---- B: zero x-pad columns (slots 0 and 33), then cp.async the 32 cols
    #pragma unroll
    for (int i = tid; i < 6 * 2 * 32; i += 512) {
        int rr = i >> 6, rem = i & 63;
        int side = rem >> 5, c4 = rem & 31;
        int xp = side ? 33 : 0;
        *reinterpret_cast<float4*>(Bs + (rr * 34 + xp) * CBST + c4 * 4) =
            make_float4(0.f, 0.f, 0.f, 0.f);
    }
    {
        const uint32_t sbB = smem_u32(Bs);
        const float* bsrc = g_pad + ((size_t)b * 34 + ytile * 4) * 32 * CDIM;
        #pragma unroll
        for (int i = 0; i < 12; i++) {           // 6144 float4 / 512
            int f = tid + i * 512;
            int c4 = f & 31, x = (f >> 5) & 31, rr = f >> 10;
            CP_ASYNC16(sbB + ((rr * 34 + x + 1) * CBST + c4 * 4) * 4,
                       bsrc + (rr * 32 + x) * CDIM + c4 * 4);
        }
        CP_COMMIT();                              // group 0: B
    }

    const float* wbase = w_t + (size_t)b * 9 * CDIM * CDIM;
    auto issueA = [&](int s) {                    // stage s: tap=s>>1, kc=s&1
        const int tap = s >> 1, kc = s & 1;
        const uint32_t sa = smem_u32(Abuf[s % 3]);
        const float* src = wbase + tap * (CDIM * CDIM) + kc * 64;
        #pragma unroll
        for (int i = 0; i < 4; i++) {             // 2048 float4 / 512
            int f = tid + i * 512;
            int r = f >> 4, k4 = f & 15;
            CP_ASYNC16(sa + (r * CAST + k4 * 4) * 4, src + r * CDIM + k4 * 4);
        }
        CP_COMMIT();
    };

    issueA(0); issueA(1); issueA(2);

    float acc[2][4][4];
    #pragma unroll
    for (int mt = 0; mt < 2; mt++)
        #pragma unroll
        for (int nt = 0; nt < 4; nt++)
            #pragma unroll
            for (int k = 0; k < 4; k++) acc[mt][nt][k] = 0.f;

    for (int s = 0; s < 18; s++) {
        if      (s < 16) CP_WAIT(2);
        else if (s == 16) CP_WAIT(1);
        else             CP_WAIT(0);
        __syncthreads();

        const int tap = s >> 1, kc = s & 1;
        const int dy = tap / 3, dx = tap % 3;
        const float* A = Abuf[s % 3];
        const float* Brow = Bs + ((pwv + dy) * 34 + dx) * CBST + kc * 64;

        #pragma unroll
        for (int j = 0; j < 8; j++) {
            float ar[2][4];
            #pragma unroll
            for (int mt = 0; mt < 2; mt++) {
                const float* ap = A + (ow * 32 + mt * 16 + g) * CAST + j * 8 + q;
                ar[mt][0] = ap[0];        ar[mt][1] = ap[8 * CAST];
                ar[mt][2] = ap[4];        ar[mt][3] = ap[8 * CAST + 4];
            }
            #pragma unroll
            for (int nt = 0; nt < 4; nt++) {
                const float* bp = Brow + (nt * 8 + g) * CBST + j * 8 + q;
                float b0 = bp[0], b1 = bp[4];
                #pragma unroll
                for (int mt = 0; mt < 2; mt++)
                    mma_tf32(acc[mt][nt], ar[mt], b0, b1);
            }
        }
        __syncthreads();
        if (s + 3 < 18) issueA(s + 3);
    }

    // Epilogue: +per-sample bias, float2 stores
    const float* bsrc = qrep + (size_t)b * WDIM + WOFF;
    #pragma unroll
    for (int mt = 0; mt < 2; mt++) {
        int o  = ow * 32 + mt * 16 + g;
        float bl = __ldg(bsrc + o), bh = __ldg(bsrc + o + 8);
        #pragma unroll
        for (int nt = 0; nt < 4; nt++) {
            int px = ytile * 128 + pwv * 32 + nt * 8 + 2 * q;
            float2 v0 = make_float2(acc[mt][nt][0] + bl, acc[mt][nt][1] + bl);
            float2 v1 = make_float2(acc[mt][nt][2] + bh, acc[mt][nt][3] + bh);
            *reinterpret_cast<float2*>(out + ((size_t)b * CDIM + o)     * NPX + px) = v0;
            *reinterpret_cast<float2*>(out + ((size_t)b * CDIM + o + 8) * NPX + px) = v1;
        }
    }
}

// ===========================================================================
extern "C" void kernel_launch(void* const* d_in, const int* in_sizes, int n_in,
                              void* d_out, int out_size)
{
    const float* qrep = (const float*)d_in[0];   // (64, 147584)
    const float* lhs  = (const float*)d_in[1];   // (64, 128, 32, 32)
    const float* rhs  = (const float*)d_in[2];   // (64, 128, 32, 32)
    const float* pw   = (const float*)d_in[3];   // (128, 256)
    const float* pb   = (const float*)d_in[4];   // (128,)
    float* out = (float*)d_out;                  // (64, 128, 32, 32)

    static bool attr_done = false;
    if (!attr_done) {
        cudaFuncSetAttribute(proj_kernel,
            cudaFuncAttributeMaxDynamicSharedMemorySize, PROJ_SMEM);
        cudaFuncSetAttribute(conv_kernel,
            cudaFuncAttributeMaxDynamicSharedMemorySize, CONV_SMEM);
        attr_done = true;
    }

    wtrans_kernel<<<dim3(CDIM, BB), 128>>>(qrep);
    proj_kernel<<<dim3(8, BB), 256, PROJ_SMEM>>>(lhs, rhs, pw, pb);
    conv_kernel<<<dim3(8, BB), 512, CONV_SMEM>>>(qrep, out);
}

// round 7
// speedup vs baseline: 3.1746x; 1.0067x over previous
#include <cuda_runtime.h>
#include <cstdint>

// Problem constants
#define BB    64
#define CDIM  128
#define NPX   1024
#define WDIM  147584          // 128*128*9 + 128
#define WOFF  147456

// ---------------------------------------------------------------------------
// Device scratch
// w_t  : tf32-rounded conv weights      [b][tap=9][o=128][c=128]
// g_pad: tf32-rounded projected input   [b][y=34][x=32][c=128]  (y pads = 0)
// ---------------------------------------------------------------------------
__device__ float w_t  [(size_t)BB * 9 * CDIM * CDIM];
__device__ float g_pad[(size_t)BB * 34 * 32 * CDIM];

// ===========================================================================
// helpers
// ===========================================================================
__device__ __forceinline__ uint32_t smem_u32(const void* p) {
    uint32_t a;
    asm("{ .reg .u64 t; cvta.to.shared.u64 t, %1; cvt.u32.u64 %0, t; }"
        : "=r"(a) : "l"(p));
    return a;
}
__device__ __forceinline__ float rna_tf32(float x) {
    uint32_t r;
    asm("cvt.rna.tf32.f32 %0, %1;" : "=r"(r) : "f"(x));
    return __uint_as_float(r);
}

#define CP_ASYNC16(dst_u32, src_ptr) \
    asm volatile("cp.async.cg.shared.global [%0], [%1], 16;" \
                 :: "r"(dst_u32), "l"(src_ptr) : "memory")
#define CP_ASYNC16Z(dst_u32, src_ptr, szr) \
    asm volatile("cp.async.cg.shared.global [%0], [%1], 16, %2;" \
                 :: "r"(dst_u32), "l"(src_ptr), "r"(szr) : "memory")
#define CP_COMMIT() asm volatile("cp.async.commit_group;" ::: "memory")
#define CP_WAIT(N)  asm volatile("cp.async.wait_group %0;" :: "n"(N) : "memory")

// m16n8k8 tf32 MMA (operands must already be tf32-rounded bit patterns)
__device__ __forceinline__ void mma_tf32(float* d, const float* a,
                                         float b0, float b1) {
    asm volatile(
        "mma.sync.aligned.m16n8k8.row.col.f32.tf32.tf32.f32 "
        "{%0,%1,%2,%3}, {%4,%5,%6,%7}, {%8,%9}, {%0,%1,%2,%3};"
        : "+f"(d[0]), "+f"(d[1]), "+f"(d[2]), "+f"(d[3])
        : "r"(__float_as_uint(a[0])), "r"(__float_as_uint(a[1])),
          "r"(__float_as_uint(a[2])), "r"(__float_as_uint(a[3])),
          "r"(__float_as_uint(b0)),   "r"(__float_as_uint(b1)));
}

// ===========================================================================
// Kernel 0: conv-weight transpose + tf32 rounding (fat blocks, smem staged)
//   w_t[b][tap][o][c] = rna(qrep[b, o*1152 + c*9 + tap])
// Grid (8 ogroups, 64 b), 256 threads, 16 o-rows per block.
// ===========================================================================
#define WT_SMEM (16 * 1152 * 4)          // 73728 B

__global__ __launch_bounds__(256) void wtrans_kernel(const float* __restrict__ qrep)
{
    extern __shared__ float s[];
    const int b = blockIdx.y, obase = blockIdx.x * 16;
    const int tid = threadIdx.x;
    const float* src = qrep + (size_t)b * WDIM + obase * 1152;

    #pragma unroll
    for (int i = 0; i < 18; i++) {                 // 4608 float4, coalesced
        int idx = tid + i * 256;
        *reinterpret_cast<float4*>(s + idx * 4) =
            *reinterpret_cast<const float4*>(src + idx * 4);
    }
    __syncthreads();

    #pragma unroll
    for (int i = 0; i < 18; i++) {                 // (tap, o, c4)
        int idx = tid + i * 256;
        int tap = idx >> 9, rem = idx & 511;
        int o = rem >> 5, c4 = rem & 31;
        const float* row = s + o * 1152 + tap;
        float4 v;
        v.x = rna_tf32(row[(c4 * 4 + 0) * 9]);
        v.y = rna_tf32(row[(c4 * 4 + 1) * 9]);
        v.z = rna_tf32(row[(c4 * 4 + 2) * 9]);
        v.w = rna_tf32(row[(c4 * 4 + 3) * 9]);
        *reinterpret_cast<float4*>(
            w_t + (((size_t)b * 9 + tap) * CDIM + obase + o) * CDIM + c4 * 4) = v;
    }
}

// ===========================================================================
// Kernel 1: projection via mma.sync tf32, rounding on register fragments.
//   g_pad[b][1+y][x][o] = rna( sum_c pw[o,c]*cat[b,c,(y,x)] + pb[o] )
// CTA: 128 o x 128 px, 8 warps (2x4), warp 64x32. K=256, 8 stages of 32.
// ===========================================================================
#define AST 36
#define PBST 136
#define PROJ_STAGE (128*AST + 32*PBST)      // 8960 floats
#define PROJ_SMEM  (2*PROJ_STAGE*4)         // 71680 B

__global__ __launch_bounds__(256) void proj_kernel(
    const float* __restrict__ lhs, const float* __restrict__ rhs,
    const float* __restrict__ pw,  const float* __restrict__ pb)
{
    extern __shared__ float sm[];
    const int tid = threadIdx.x, lane = tid & 31, warp = tid >> 5;
    const int g = lane >> 2, q = lane & 3;
    const int ow = warp & 1, pwv = warp >> 1;
    const int b = blockIdx.y, pxbase = blockIdx.x * 128;

    float* bufA[2] = { sm,              sm + PROJ_STAGE };
    float* bufB[2] = { sm + 128 * AST,  sm + PROJ_STAGE + 128 * AST };

    auto issue = [&](int s) {
        const int cb = s * 32, buf = s & 1;
        const uint32_t sa = smem_u32(bufA[buf]);
        const uint32_t sb = smem_u32(bufB[buf]);
        #pragma unroll
        for (int i = 0; i < 4; i++) {           // A: 128 o x 32 k (raw pw)
            int f = tid + i * 256;
            int r = f >> 3, k4 = f & 7;
            CP_ASYNC16(sa + (r * AST + k4 * 4) * 4, pw + r * 256 + cb + k4 * 4);
        }
        #pragma unroll
        for (int i = 0; i < 4; i++) {           // B: 32 k x 128 px (raw cat)
            int f = tid + i * 256;
            int kr = f >> 5, n4 = f & 31;
            int c  = cb + kr;
            const float* src = (c < CDIM)
                ? (lhs + ((size_t)b * CDIM + c) * NPX + pxbase + n4 * 4)
                : (rhs + ((size_t)b * CDIM + (c - CDIM)) * NPX + pxbase + n4 * 4);
            CP_ASYNC16(sb + (kr * PBST + n4 * 4) * 4, src);
        }
        CP_COMMIT();
    };

    float acc[4][4][4];
    #pragma unroll
    for (int mt = 0; mt < 4; mt++)
        #pragma unroll
        for (int nt = 0; nt < 4; nt++)
            #pragma unroll
            for (int k = 0; k < 4; k++) acc[mt][nt][k] = 0.f;

    issue(0);
    for (int s = 0; s < 8; s++) {
        if (s + 1 < 8) { issue(s + 1); CP_WAIT(1); }
        else           { CP_WAIT(0); }
        __syncthreads();
        const float* A  = bufA[s & 1];
        const float* Bm = bufB[s & 1];
        #pragma unroll
        for (int j = 0; j < 4; j++) {
            float ar[4][4];
            #pragma unroll
            for (int mt = 0; mt < 4; mt++) {
                const float* ap = A + (ow * 64 + mt * 16 + g) * AST + j * 8 + q;
                ar[mt][0] = rna_tf32(ap[0]);
                ar[mt][1] = rna_tf32(ap[8 * AST]);
                ar[mt][2] = rna_tf32(ap[4]);
                ar[mt][3] = rna_tf32(ap[8 * AST + 4]);
            }
            #pragma unroll
            for (int nt = 0; nt < 4; nt++) {
                const float* bp = Bm + (j * 8 + q) * PBST + pwv * 32 + nt * 8 + g;
                float b0 = rna_tf32(bp[0]), b1 = rna_tf32(bp[4 * PBST]);
                #pragma unroll
                for (int mt = 0; mt < 4; mt++)
                    mma_tf32(acc[mt][nt], ar[mt], b0, b1);
            }
        }
        __syncthreads();
    }

    // Epilogue: +bias, rna, transpose through smem, coalesced store to g_pad
    float* T = sm;                               // [128 px][132]
    #pragma unroll
    for (int mt = 0; mt < 4; mt++) {
        int o = ow * 64 + mt * 16 + g;
        float bl = __ldg(pb + o), bh = __ldg(pb + o + 8);
        #pragma unroll
        for (int nt = 0; nt < 4; nt++) {
            int n0 = pwv * 32 + nt * 8 + 2 * q;
            T[n0 * 132 + o]           = rna_tf32(acc[mt][nt][0] + bl);
            T[(n0 + 1) * 132 + o]     = rna_tf32(acc[mt][nt][1] + bl);
            T[n0 * 132 + o + 8]       = rna_tf32(acc[mt][nt][2] + bh);
            T[(n0 + 1) * 132 + o + 8] = rna_tf32(acc[mt][nt][3] + bh);
        }
    }
    __syncthreads();
    #pragma unroll
    for (int i = 0; i < 16; i++) {
        int idx = tid + i * 256;
        int row = idx >> 5, c4 = idx & 31;
        int px = pxbase + row, y = px >> 5, x = px & 31;
        float4 v = *reinterpret_cast<const float4*>(T + row * 132 + c4 * 4);
        *reinterpret_cast<float4*>(
            g_pad + (((size_t)b * 34 + 1 + y) * 32 + x) * CDIM + c4 * 4) = v;
    }
}

// ===========================================================================
// Kernel 2: conv as shifted-tap implicit GEMM, streaming A+B,
// 3-stage ring buffer / 2-deep prefetch / ONE sync per stage.
// CTA: 128 o x 128 px, 256 thr, 8 warps (2o x 4px), warp 64x32.
// 36 stages (9 taps x 4 k-chunks of 32). smem 110.6 KB -> 2 CTA/SM.
// ===========================================================================
#define CONV_STAGE (2*128*AST)                  // 9216 floats
#define CONV_SMEM  (3*CONV_STAGE*4)             // 110592 B
#define NSTG 36

__global__ __launch_bounds__(256, 2) void conv_kernel(
    const float* __restrict__ qrep, float* __restrict__ out)
{
    extern __shared__ float sm[];
    const int tid = threadIdx.x, lane = tid & 31, warp = tid >> 5;
    const int g = lane >> 2, q = lane & 3;
    const int ow = warp & 1, pwv = warp >> 1;
    const int ytile = blockIdx.x, b = blockIdx.y;

    float* bufA[3] = { sm, sm + CONV_STAGE, sm + 2 * CONV_STAGE };
    float* bufB[3] = { sm + 128 * AST, sm + CONV_STAGE + 128 * AST,
                       sm + 2 * CONV_STAGE + 128 * AST };

    const float* wbase = w_t + (size_t)b * 9 * CDIM * CDIM;

    auto issue = [&](int s) {
        const int tap = s >> 2, kc = s & 3, buf = s % 3;
        const int dy = tap / 3, dx = tap % 3;
        const uint32_t sa = smem_u32(bufA[buf]);
        const uint32_t sb = smem_u32(bufB[buf]);
        const float* wsrc = wbase + tap * (CDIM * CDIM) + kc * 32;
        #pragma unroll
        for (int i = 0; i < 4; i++) {           // A: 128 o x 32 k
            int f = tid + i * 256;
            int r = f >> 3, k4 = f & 7;
            CP_ASYNC16(sa + (r * AST + k4 * 4) * 4, wsrc + r * CDIM + k4 * 4);
        }
        #pragma unroll
        for (int i = 0; i < 4; i++) {           // B: 128 px x 32 k (shifted)
            int f = tid + i * 256;
            int r = f >> 3, k4 = f & 7;
            int x = r & 31, rr = r >> 5;
            int xin = x + dx - 1;
            int ok  = ((unsigned)xin < 32u) ? 16 : 0;
            int xc  = xin < 0 ? 0 : (xin > 31 ? 31 : xin);
            int row = ytile * 4 + dy + rr;
            const float* src = g_pad + (((size_t)b * 34 + row) * 32 + xc) * CDIM
                                     + kc * 32 + k4 * 4;
            CP_ASYNC16Z(sb + (r * AST + k4 * 4) * 4, src, ok);
        }
        CP_COMMIT();
    };

    float acc[4][4][4];
    #pragma unroll
    for (int mt = 0; mt < 4; mt++)
        #pragma unroll
        for (int nt = 0; nt < 4; nt++)
            #pragma unroll
            for (int k = 0; k < 4; k++) acc[mt][nt][k] = 0.f;

    issue(0); issue(1);

    for (int s = 0; s < NSTG; s++) {
        if (s + 1 < NSTG) CP_WAIT(1);
        else              CP_WAIT(0);
        __syncthreads();                         // one barrier per stage
        if (s + 2 < NSTG) issue(s + 2);          // refills buffer (s-1)%3

        const float* A  = bufA[s % 3];
        const float* Bm = bufB[s % 3];
        #pragma unroll
        for (int j = 0; j < 4; j++) {
            float ar[4][4];
            #pragma unroll
            for (int mt = 0; mt < 4; mt++) {
                const float* ap = A + (ow * 64 + mt * 16 + g) * AST + j * 8 + q;
                ar[mt][0] = ap[0];        ar[mt][1] = ap[8 * AST];
                ar[mt][2] = ap[4];        ar[mt][3] = ap[8 * AST + 4];
            }
            #pragma unroll
            for (int nt = 0; nt < 4; nt++) {
                const float* bp = Bm + (pwv * 32 + nt * 8 + g) * AST + j * 8 + q;
                float b0 = bp[0], b1 = bp[4];
                #pragma unroll
                for (int mt = 0; mt < 4; mt++)
                    mma_tf32(acc[mt][nt], ar[mt], b0, b1);
            }
        }
    }

    // Epilogue: +per-sample bias, float2 stores
    const float* bsrc = qrep + (size_t)b * WDIM + WOFF;
    #pragma unroll
    for (int mt = 0; mt < 4; mt++) {
        int o  = ow * 64 + mt * 16 + g;
        float bl = __ldg(bsrc + o), bh = __ldg(bsrc + o + 8);
        #pragma unroll
        for (int nt = 0; nt < 4; nt++) {
            int px = ytile * 128 + pwv * 32 + nt * 8 + 2 * q;
            float2 v0 = make_float2(acc[mt][nt][0] + bl, acc[mt][nt][1] + bl);
            float2 v1 = make_float2(acc[mt][nt][2] + bh, acc[mt][nt][3] + bh);
            *reinterpret_cast<float2*>(out + ((size_t)b * CDIM + o)     * NPX + px) = v0;
            *reinterpret_cast<float2*>(out + ((size_t)b * CDIM + o + 8) * NPX + px) = v1;
        }
    }
}

// ===========================================================================
extern "C" void kernel_launch(void* const* d_in, const int* in_sizes, int n_in,
                              void* d_out, int out_size)
{
    const float* qrep = (const float*)d_in[0];   // (64, 147584)
    const float* lhs  = (const float*)d_in[1];   // (64, 128, 32, 32)
    const float* rhs  = (const float*)d_in[2];   // (64, 128, 32, 32)
    const float* pw   = (const float*)d_in[3];   // (128, 256)
    const float* pb   = (const float*)d_in[4];   // (128,)
    float* out = (float*)d_out;                  // (64, 128, 32, 32)

    static bool attr_done = false;
    if (!attr_done) {
        cudaFuncSetAttribute(wtrans_kernel,
            cudaFuncAttributeMaxDynamicSharedMemorySize, WT_SMEM);
        cudaFuncSetAttribute(proj_kernel,
            cudaFuncAttributeMaxDynamicSharedMemorySize, PROJ_SMEM);
        cudaFuncSetAttribute(conv_kernel,
            cudaFuncAttributeMaxDynamicSharedMemorySize, CONV_SMEM);
        attr_done = true;
    }

    wtrans_kernel<<<dim3(8, BB), 256, WT_SMEM>>>(qrep);
    proj_kernel<<<dim3(8, BB), 256, PROJ_SMEM>>>(lhs, rhs, pw, pb);
    conv_kernel<<<dim3(8, BB), 256, CONV_SMEM>>>(qrep, out);
}

// round 9
// speedup vs baseline: 5.7558x; 1.8131x over previous
#include <cuda_runtime.h>
#include <cuda_fp16.h>
#include <cstdint>

// Problem constants
#define BB    64
#define CDIM  128
#define NPX   1024
#define WDIM  147584          // 128*128*9 + 128
#define WOFF  147456

// ---------------------------------------------------------------------------
// Device scratch
// w_h   : fp16 conv weights            [b][tap=9][o=128][c=128]
// g_padh: fp16 projected input         [b][y=34][x=32][c=128]  (y pads = 0)
// ---------------------------------------------------------------------------
__device__ __half w_h  [(size_t)BB * 9 * CDIM * CDIM];
__device__ __half g_padh[(size_t)BB * 34 * 32 * CDIM];

// ===========================================================================
// helpers
// ===========================================================================
__device__ __forceinline__ uint32_t smem_u32(const void* p) {
    uint32_t a;
    asm("{ .reg .u64 t; cvta.to.shared.u64 t, %1; cvt.u32.u64 %0, t; }"
        : "=r"(a) : "l"(p));
    return a;
}
__device__ __forceinline__ float rna_tf32(float x) {
    uint32_t r;
    asm("cvt.rna.tf32.f32 %0, %1;" : "=r"(r) : "f"(x));
    return __uint_as_float(r);
}

#define CP_ASYNC16(dst_u32, src_ptr) \
    asm volatile("cp.async.cg.shared.global [%0], [%1], 16;" \
                 :: "r"(dst_u32), "l"(src_ptr) : "memory")
#define CP_ASYNC16Z(dst_u32, src_ptr, szr) \
    asm volatile("cp.async.cg.shared.global [%0], [%1], 16, %2;" \
                 :: "r"(dst_u32), "l"(src_ptr), "r"(szr) : "memory")
#define CP_COMMIT() asm volatile("cp.async.commit_group;" ::: "memory")
#define CP_WAIT(N)  asm volatile("cp.async.wait_group %0;" :: "n"(N) : "memory")

#define LDSM_X4(r0,r1,r2,r3,addr) \
    asm volatile("ldmatrix.sync.aligned.m8n8.x4.shared.b16 {%0,%1,%2,%3}, [%4];" \
                 : "=r"(r0),"=r"(r1),"=r"(r2),"=r"(r3) : "r"(addr))

// m16n8k8 tf32 MMA (proj kernel)
__device__ __forceinline__ void mma_tf32(float* d, const float* a,
                                         float b0, float b1) {
    asm volatile(
        "mma.sync.aligned.m16n8k8.row.col.f32.tf32.tf32.f32 "
        "{%0,%1,%2,%3}, {%4,%5,%6,%7}, {%8,%9}, {%0,%1,%2,%3};"
        : "+f"(d[0]), "+f"(d[1]), "+f"(d[2]), "+f"(d[3])
        : "r"(__float_as_uint(a[0])), "r"(__float_as_uint(a[1])),
          "r"(__float_as_uint(a[2])), "r"(__float_as_uint(a[3])),
          "r"(__float_as_uint(b0)),   "r"(__float_as_uint(b1)));
}

// m16n8k16 fp16 MMA, fp32 accumulate (conv kernel)
__device__ __forceinline__ void mma_f16(float* d, const uint32_t* a,
                                        uint32_t b0, uint32_t b1) {
    asm volatile(
        "mma.sync.aligned.m16n8k16.row.col.f32.f16.f16.f32 "
        "{%0,%1,%2,%3}, {%4,%5,%6,%7}, {%8,%9}, {%0,%1,%2,%3};"
        : "+f"(d[0]), "+f"(d[1]), "+f"(d[2]), "+f"(d[3])
        : "r"(a[0]), "r"(a[1]), "r"(a[2]), "r"(a[3]), "r"(b0), "r"(b1));
}

// ===========================================================================
// Kernel 0: conv-weight transpose + fp16 conversion
//   w_h[b][tap][o][c] = half(qrep[b, o*1152 + c*9 + tap])
// Grid (8 ogroups, 64 b), 256 threads, 16 o-rows per block.
// ===========================================================================
#define WT_SMEM (16 * 1152 * 4)          // 73728 B

__global__ __launch_bounds__(256) void wtrans_kernel(const float* __restrict__ qrep)
{
    extern __shared__ float s[];
    const int b = blockIdx.y, obase = blockIdx.x * 16;
    const int tid = threadIdx.x;
    const float* src = qrep + (size_t)b * WDIM + obase * 1152;

    #pragma unroll
    for (int i = 0; i < 18; i++) {
        int idx = tid + i * 256;
        *reinterpret_cast<float4*>(s + idx * 4) =
            *reinterpret_cast<const float4*>(src + idx * 4);
    }
    __syncthreads();

    #pragma unroll
    for (int i = 0; i < 18; i++) {                 // (tap, o, c4)
        int idx = tid + i * 256;
        int tap = idx >> 9, rem = idx & 511;
        int o = rem >> 5, c4 = rem & 31;
        const float* row = s + o * 1152 + tap;
        __half2 h0 = __floats2half2_rn(row[(c4 * 4 + 0) * 9], row[(c4 * 4 + 1) * 9]);
        __half2 h1 = __floats2half2_rn(row[(c4 * 4 + 2) * 9], row[(c4 * 4 + 3) * 9]);
        uint2 u;
        u.x = *reinterpret_cast<uint32_t*>(&h0);
        u.y = *reinterpret_cast<uint32_t*>(&h1);
        *reinterpret_cast<uint2*>(
            w_h + (((size_t)b * 9 + tap) * CDIM + obase + o) * CDIM + c4 * 4) = u;
    }
}

// ===========================================================================
// Kernel 1: projection via mma.sync tf32, fp16 output.
//   g_padh[b][1+y][x][o] = half( sum_c pw[o,c]*cat[b,c,(y,x)] + pb[o] )
// CTA: 128 o x 128 px, 8 warps (2x4), warp 64x32. K=256, 8 stages of 32.
// ===========================================================================
#define AST 36
#define PBST 136
#define PROJ_STAGE (128*AST + 32*PBST)      // 8960 floats
#define PROJ_SMEM  (2*PROJ_STAGE*4)         // 71680 B

__global__ __launch_bounds__(256) void proj_kernel(
    const float* __restrict__ lhs, const float* __restrict__ rhs,
    const float* __restrict__ pw,  const float* __restrict__ pb)
{
    extern __shared__ float sm[];
    const int tid = threadIdx.x, lane = tid & 31, warp = tid >> 5;
    const int g = lane >> 2, q = lane & 3;
    const int ow = warp & 1, pwv = warp >> 1;
    const int b = blockIdx.y, pxbase = blockIdx.x * 128;

    float* bufA[2] = { sm,              sm + PROJ_STAGE };
    float* bufB[2] = { sm + 128 * AST,  sm + PROJ_STAGE + 128 * AST };

    auto issue = [&](int s) {
        const int cb = s * 32, buf = s & 1;
        const uint32_t sa = smem_u32(bufA[buf]);
        const uint32_t sb = smem_u32(bufB[buf]);
        #pragma unroll
        for (int i = 0; i < 4; i++) {           // A: 128 o x 32 k (raw pw)
            int f = tid + i * 256;
            int r = f >> 3, k4 = f & 7;
            CP_ASYNC16(sa + (r * AST + k4 * 4) * 4, pw + r * 256 + cb + k4 * 4);
        }
        #pragma unroll
        for (int i = 0; i < 4; i++) {           // B: 32 k x 128 px (raw cat)
            int f = tid + i * 256;
            int kr = f >> 5, n4 = f & 31;
            int c  = cb + kr;
            const float* src = (c < CDIM)
                ? (lhs + ((size_t)b * CDIM + c) * NPX + pxbase + n4 * 4)
                : (rhs + ((size_t)b * CDIM + (c - CDIM)) * NPX + pxbase + n4 * 4);
            CP_ASYNC16(sb + (kr * PBST + n4 * 4) * 4, src);
        }
        CP_COMMIT();
    };

    float acc[4][4][4];
    #pragma unroll
    for (int mt = 0; mt < 4; mt++)
        #pragma unroll
        for (int nt = 0; nt < 4; nt++)
            #pragma unroll
            for (int k = 0; k < 4; k++) acc[mt][nt][k] = 0.f;

    issue(0);
    for (int s = 0; s < 8; s++) {
        if (s + 1 < 8) { issue(s + 1); CP_WAIT(1); }
        else           { CP_WAIT(0); }
        __syncthreads();
        const float* A  = bufA[s & 1];
        const float* Bm = bufB[s & 1];
        #pragma unroll
        for (int j = 0; j < 4; j++) {
            float ar[4][4];
            #pragma unroll
            for (int mt = 0; mt < 4; mt++) {
                const float* ap = A + (ow * 64 + mt * 16 + g) * AST + j * 8 + q;
                ar[mt][0] = rna_tf32(ap[0]);
                ar[mt][1] = rna_tf32(ap[8 * AST]);
                ar[mt][2] = rna_tf32(ap[4]);
                ar[mt][3] = rna_tf32(ap[8 * AST + 4]);
            }
            #pragma unroll
            for (int nt = 0; nt < 4; nt++) {
                const float* bp = Bm + (j * 8 + q) * PBST + pwv * 32 + nt * 8 + g;
                float b0 = rna_tf32(bp[0]), b1 = rna_tf32(bp[4 * PBST]);
                #pragma unroll
                for (int mt = 0; mt < 4; mt++)
                    mma_tf32(acc[mt][nt], ar[mt], b0, b1);
            }
        }
        __syncthreads();
    }

    // Epilogue: +bias, transpose through smem, fp16 store to g_padh
    float* T = sm;                               // [128 px][132]
    #pragma unroll
    for (int mt = 0; mt < 4; mt++) {
        int o = ow * 64 + mt * 16 + g;
        float bl = __ldg(pb + o), bh = __ldg(pb + o + 8);
        #pragma unroll
        for (int nt = 0; nt < 4; nt++) {
            int n0 = pwv * 32 + nt * 8 + 2 * q;
            T[n0 * 132 + o]           = acc[mt][nt][0] + bl;
            T[(n0 + 1) * 132 + o]     = acc[mt][nt][1] + bl;
            T[n0 * 132 + o + 8]       = acc[mt][nt][2] + bh;
            T[(n0 + 1) * 132 + o + 8] = acc[mt][nt][3] + bh;
        }
    }
    __syncthreads();
    #pragma unroll
    for (int i = 0; i < 16; i++) {
        int idx = tid + i * 256;
        int row = idx >> 5, c4 = idx & 31;
        int px = pxbase + row, y = px >> 5, x = px & 31;
        float4 v = *reinterpret_cast<const float4*>(T + row * 132 + c4 * 4);
        __half2 h0 = __floats2half2_rn(v.x, v.y);
        __half2 h1 = __floats2half2_rn(v.z, v.w);
        uint2 u;
        u.x = *reinterpret_cast<uint32_t*>(&h0);
        u.y = *reinterpret_cast<uint32_t*>(&h1);
        *reinterpret_cast<uint2*>(
            g_padh + (((size_t)b * 34 + 1 + y) * 32 + x) * CDIM + c4 * 4) = u;
    }
}

// ===========================================================================
// Kernel 2: conv as shifted-tap implicit GEMM, fp16 m16n8k16 + ldmatrix.
// CTA: 128 o x 128 px, 256 thr, 8 warps (2o x 4px), warp 64x32.
// 18 stages (9 taps x 2 k-chunks of 64). 3-stage ring, 1 sync/stage.
// B fragments use NON-trans ldmatrix: [n][k] rows give n=l/4, consecutive-k
// pairs, exactly the mma.row.col B fragment. (R8 bug was .trans here.)
// ===========================================================================
#define CAH 72                                   // halves per smem row
#define CONV_OP (128 * CAH)                      // 9216 halves per operand
#define CONV_STG (2 * CONV_OP)                   // A + B per stage
#define CONV_SMEM (3 * CONV_STG * 2)             // 110592 B
#define NSTG 18

__global__ __launch_bounds__(256, 2) void conv_kernel(
    const float* __restrict__ qrep, float* __restrict__ out)
{
    extern __shared__ __half smh[];
    const int tid = threadIdx.x, lane = tid & 31, warp = tid >> 5;
    const int g = lane >> 2, q = lane & 3;
    const int ow = warp & 1, pwv = warp >> 1;
    const int ytile = blockIdx.x, b = blockIdx.y;
    const uint32_t sbase = smem_u32(smh);

    const __half* wbase = w_h + (size_t)b * 9 * CDIM * CDIM;

    auto issue = [&](int s) {
        const int tap = s >> 1, kc = s & 1, buf = s % 3;
        const int dy = tap / 3, dx = tap % 3;
        const uint32_t sa = sbase + (buf * CONV_STG) * 2;
        const uint32_t sb = sa + CONV_OP * 2;
        const __half* wsrc = wbase + tap * (CDIM * CDIM) + kc * 64;
        #pragma unroll
        for (int i = 0; i < 4; i++) {           // A: 128 o x 64 k halves
            int f = tid + i * 256;
            int r = f >> 3, k16 = f & 7;        // k16: 16B unit = 8 halves
            CP_ASYNC16(sa + (r * CAH + k16 * 8) * 2, wsrc + r * CDIM + k16 * 8);
        }
        #pragma unroll
        for (int i = 0; i < 4; i++) {           // B: 128 px x 64 k (x-shifted)
            int f = tid + i * 256;
            int r = f >> 3, k16 = f & 7;
            int x = r & 31, rr = r >> 5;
            int xin = x + dx - 1;
            int ok  = ((unsigned)xin < 32u) ? 16 : 0;
            int xc  = xin < 0 ? 0 : (xin > 31 ? 31 : xin);
            int row = ytile * 4 + dy + rr;
            const __half* src = g_padh + (((size_t)b * 34 + row) * 32 + xc) * CDIM
                                       + kc * 64 + k16 * 8;
            CP_ASYNC16Z(sb + (r * CAH + k16 * 8) * 2, src, ok);
        }
        CP_COMMIT();
    };

    // ldmatrix per-lane offsets (halves); same pattern for A and B (non-trans)
    const int aRow = ((lane >> 3) & 1) * 8 + (lane & 7);
    const int aK   = (lane >> 4) * 8;
    const int m    = lane >> 3;
    const int bRow = (m >> 1) * 8 + (lane & 7);
    const int bK   = (m & 1) * 8;

    float acc[4][4][4];
    #pragma unroll
    for (int mt = 0; mt < 4; mt++)
        #pragma unroll
        for (int nt = 0; nt < 4; nt++)
            #pragma unroll
            for (int k = 0; k < 4; k++) acc[mt][nt][k] = 0.f;

    issue(0); issue(1);

    for (int s = 0; s < NSTG; s++) {
        if (s + 1 < NSTG) CP_WAIT(1);
        else              CP_WAIT(0);
        __syncthreads();
        if (s + 2 < NSTG) issue(s + 2);

        const uint32_t aBase = sbase + ((s % 3) * CONV_STG) * 2;
        const uint32_t bBase = aBase + CONV_OP * 2;

        #pragma unroll
        for (int j = 0; j < 4; j++) {           // k16 step within k64
            uint32_t af[4][4], bf[2][4];
            #pragma unroll
            for (int mt = 0; mt < 4; mt++) {
                uint32_t addr = aBase +
                    ((ow * 64 + mt * 16 + aRow) * CAH + j * 16 + aK) * 2;
                LDSM_X4(af[mt][0], af[mt][1], af[mt][2], af[mt][3], addr);
            }
            #pragma unroll
            for (int ntp = 0; ntp < 2; ntp++) {
                uint32_t addr = bBase +
                    ((pwv * 32 + ntp * 16 + bRow) * CAH + j * 16 + bK) * 2;
                LDSM_X4(bf[ntp][0], bf[ntp][1], bf[ntp][2], bf[ntp][3], addr);
            }
            #pragma unroll
            for (int nt = 0; nt < 4; nt++) {
                uint32_t b0 = bf[nt >> 1][(nt & 1) * 2];
                uint32_t b1 = bf[nt >> 1][(nt & 1) * 2 + 1];
                #pragma unroll
                for (int mt = 0; mt < 4; mt++)
                    mma_f16(acc[mt][nt], af[mt], b0, b1);
            }
        }
    }

    // Epilogue: +per-sample bias, float2 stores
    const float* bsrc = qrep + (size_t)b * WDIM + WOFF;
    #pragma unroll
    for (int mt = 0; mt < 4; mt++) {
        int o  = ow * 64 + mt * 16 + g;
        float bl = __ldg(bsrc + o), bh = __ldg(bsrc + o + 8);
        #pragma unroll
        for (int nt = 0; nt < 4; nt++) {
            int px = ytile * 128 + pwv * 32 + nt * 8 + 2 * q;
            float2 v0 = make_float2(acc[mt][nt][0] + bl, acc[mt][nt][1] + bl);
            float2 v1 = make_float2(acc[mt][nt][2] + bh, acc[mt][nt][3] + bh);
            *reinterpret_cast<float2*>(out + ((size_t)b * CDIM + o)     * NPX + px) = v0;
            *reinterpret_cast<float2*>(out + ((size_t)b * CDIM + o + 8) * NPX + px) = v1;
        }
    }
}

// ===========================================================================
extern "C" void kernel_launch(void* const* d_in, const int* in_sizes, int n_in,
                              void* d_out, int out_size)
{
    const float* qrep = (const float*)d_in[0];   // (64, 147584)
    const float* lhs  = (const float*)d_in[1];   // (64, 128, 32, 32)
    const float* rhs  = (const float*)d_in[2];   // (64, 128, 32, 32)
    const float* pw   = (const float*)d_in[3];   // (128, 256)
    const float* pb   = (const float*)d_in[4];   // (128,)
    float* out = (float*)d_out;                  // (64, 128, 32, 32)

    static bool attr_done = false;
    if (!attr_done) {
        cudaFuncSetAttribute(wtrans_kernel,
            cudaFuncAttributeMaxDynamicSharedMemorySize, WT_SMEM);
        cudaFuncSetAttribute(proj_kernel,
            cudaFuncAttributeMaxDynamicSharedMemorySize, PROJ_SMEM);
        cudaFuncSetAttribute(conv_kernel,
            cudaFuncAttributeMaxDynamicSharedMemorySize, CONV_SMEM);
        attr_done = true;
    }

    wtrans_kernel<<<dim3(8, BB), 256, WT_SMEM>>>(qrep);
    proj_kernel<<<dim3(8, BB), 256, PROJ_SMEM>>>(lhs, rhs, pw, pb);
    conv_kernel<<<dim3(8, BB), 256, CONV_SMEM>>>(qrep, out);
}

// round 10
// speedup vs baseline: 6.6738x; 1.1595x over previous
#include <cuda_runtime.h>
#include <cuda_fp16.h>
#include <cstdint>

// Problem constants
#define BB    64
#define CDIM  128
#define NPX   1024
#define WDIM  147584          // 128*128*9 + 128
#define WOFF  147456

// ---------------------------------------------------------------------------
// Device scratch
// w_h   : fp16 conv weights            [b][tap=9][o=128][c=128]
// g_padh: fp16 projected input         [b][y=34][x=32][c=128]  (y pads = 0)
// ---------------------------------------------------------------------------
__device__ __half w_h  [(size_t)BB * 9 * CDIM * CDIM];
__device__ __half g_padh[(size_t)BB * 34 * 32 * CDIM];

// ===========================================================================
// helpers
// ===========================================================================
__device__ __forceinline__ uint32_t smem_u32(const void* p) {
    uint32_t a;
    asm("{ .reg .u64 t; cvta.to.shared.u64 t, %1; cvt.u32.u64 %0, t; }"
        : "=r"(a) : "l"(p));
    return a;
}
__device__ __forceinline__ float rna_tf32(float x) {
    uint32_t r;
    asm("cvt.rna.tf32.f32 %0, %1;" : "=r"(r) : "f"(x));
    return __uint_as_float(r);
}

#define CP_ASYNC16(dst_u32, src_ptr) \
    asm volatile("cp.async.cg.shared.global [%0], [%1], 16;" \
                 :: "r"(dst_u32), "l"(src_ptr) : "memory")
#define CP_COMMIT() asm volatile("cp.async.commit_group;" ::: "memory")
#define CP_WAIT(N)  asm volatile("cp.async.wait_group %0;" :: "n"(N) : "memory")

#define LDSM_X4(r0,r1,r2,r3,addr) \
    asm volatile("ldmatrix.sync.aligned.m8n8.x4.shared.b16 {%0,%1,%2,%3}, [%4];" \
                 : "=r"(r0),"=r"(r1),"=r"(r2),"=r"(r3) : "r"(addr))

// m16n8k8 tf32 MMA (proj kernel)
__device__ __forceinline__ void mma_tf32(float* d, const float* a,
                                         float b0, float b1) {
    asm volatile(
        "mma.sync.aligned.m16n8k8.row.col.f32.tf32.tf32.f32 "
        "{%0,%1,%2,%3}, {%4,%5,%6,%7}, {%8,%9}, {%0,%1,%2,%3};"
        : "+f"(d[0]), "+f"(d[1]), "+f"(d[2]), "+f"(d[3])
        : "r"(__float_as_uint(a[0])), "r"(__float_as_uint(a[1])),
          "r"(__float_as_uint(a[2])), "r"(__float_as_uint(a[3])),
          "r"(__float_as_uint(b0)),   "r"(__float_as_uint(b1)));
}

// m16n8k16 fp16 MMA, fp32 accumulate (conv kernel)
__device__ __forceinline__ void mma_f16(float* d, const uint32_t* a,
                                        uint32_t b0, uint32_t b1) {
    asm volatile(
        "mma.sync.aligned.m16n8k16.row.col.f32.f16.f16.f32 "
        "{%0,%1,%2,%3}, {%4,%5,%6,%7}, {%8,%9}, {%0,%1,%2,%3};"
        : "+f"(d[0]), "+f"(d[1]), "+f"(d[2]), "+f"(d[3])
        : "r"(a[0]), "r"(a[1]), "r"(a[2]), "r"(a[3]), "r"(b0), "r"(b1));
}

// ===========================================================================
// Kernel 0: conv-weight transpose + fp16 conversion
//   w_h[b][tap][o][c] = half(qrep[b, o*1152 + c*9 + tap])
// ===========================================================================
#define WT_SMEM (16 * 1152 * 4)          // 73728 B

__global__ __launch_bounds__(256) void wtrans_kernel(const float* __restrict__ qrep)
{
    extern __shared__ float s[];
    const int b = blockIdx.y, obase = blockIdx.x * 16;
    const int tid = threadIdx.x;
    const float* src = qrep + (size_t)b * WDIM + obase * 1152;

    #pragma unroll
    for (int i = 0; i < 18; i++) {
        int idx = tid + i * 256;
        *reinterpret_cast<float4*>(s + idx * 4) =
            *reinterpret_cast<const float4*>(src + idx * 4);
    }
    __syncthreads();

    #pragma unroll
    for (int i = 0; i < 18; i++) {                 // (tap, o, c4)
        int idx = tid + i * 256;
        int tap = idx >> 9, rem = idx & 511;
        int o = rem >> 5, c4 = rem & 31;
        const float* row = s + o * 1152 + tap;
        __half2 h0 = __floats2half2_rn(row[(c4 * 4 + 0) * 9], row[(c4 * 4 + 1) * 9]);
        __half2 h1 = __floats2half2_rn(row[(c4 * 4 + 2) * 9], row[(c4 * 4 + 3) * 9]);
        uint2 u;
        u.x = *reinterpret_cast<uint32_t*>(&h0);
        u.y = *reinterpret_cast<uint32_t*>(&h1);
        *reinterpret_cast<uint2*>(
            w_h + (((size_t)b * 9 + tap) * CDIM + obase + o) * CDIM + c4 * 4) = u;
    }
}

// ===========================================================================
// Kernel 1: projection via mma.sync tf32, fp16 output.
// 3-stage ring, ONE sync per stage. K=256, 8 stages of 32.
// ===========================================================================
#define AST 36
#define PBST 136
#define PROJ_STAGE (128*AST + 32*PBST)      // 8960 floats
#define PROJ_SMEM  (3*PROJ_STAGE*4)         // 107520 B

__global__ __launch_bounds__(256, 2) void proj_kernel(
    const float* __restrict__ lhs, const float* __restrict__ rhs,
    const float* __restrict__ pw,  const float* __restrict__ pb)
{
    extern __shared__ float sm[];
    const int tid = threadIdx.x, lane = tid & 31, warp = tid >> 5;
    const int g = lane >> 2, q = lane & 3;
    const int ow = warp & 1, pwv = warp >> 1;
    const int b = blockIdx.y, pxbase = blockIdx.x * 128;

    auto issue = [&](int s) {
        const int cb = s * 32, buf = s % 3;
        const uint32_t sa = smem_u32(sm + buf * PROJ_STAGE);
        const uint32_t sb = sa + 128 * AST * 4;
        #pragma unroll
        for (int i = 0; i < 4; i++) {           // A: 128 o x 32 k (raw pw)
            int f = tid + i * 256;
            int r = f >> 3, k4 = f & 7;
            CP_ASYNC16(sa + (r * AST + k4 * 4) * 4, pw + r * 256 + cb + k4 * 4);
        }
        #pragma unroll
        for (int i = 0; i < 4; i++) {           // B: 32 k x 128 px (raw cat)
            int f = tid + i * 256;
            int kr = f >> 5, n4 = f & 31;
            int c  = cb + kr;
            const float* src = (c < CDIM)
                ? (lhs + ((size_t)b * CDIM + c) * NPX + pxbase + n4 * 4)
                : (rhs + ((size_t)b * CDIM + (c - CDIM)) * NPX + pxbase + n4 * 4);
            CP_ASYNC16(sb + (kr * PBST + n4 * 4) * 4, src);
        }
        CP_COMMIT();
    };

    float acc[4][4][4];
    #pragma unroll
    for (int mt = 0; mt < 4; mt++)
        #pragma unroll
        for (int nt = 0; nt < 4; nt++)
            #pragma unroll
            for (int k = 0; k < 4; k++) acc[mt][nt][k] = 0.f;

    issue(0); issue(1);
    for (int s = 0; s < 8; s++) {
        if (s + 1 < 8) CP_WAIT(1);
        else           CP_WAIT(0);
        __syncthreads();
        if (s + 2 < 8) issue(s + 2);

        const float* A  = sm + (s % 3) * PROJ_STAGE;
        const float* Bm = A + 128 * AST;
        #pragma unroll
        for (int j = 0; j < 4; j++) {
            float ar[4][4];
            #pragma unroll
            for (int mt = 0; mt < 4; mt++) {
                const float* ap = A + (ow * 64 + mt * 16 + g) * AST + j * 8 + q;
                ar[mt][0] = rna_tf32(ap[0]);
                ar[mt][1] = rna_tf32(ap[8 * AST]);
                ar[mt][2] = rna_tf32(ap[4]);
                ar[mt][3] = rna_tf32(ap[8 * AST + 4]);
            }
            #pragma unroll
            for (int nt = 0; nt < 4; nt++) {
                const float* bp = Bm + (j * 8 + q) * PBST + pwv * 32 + nt * 8 + g;
                float b0 = rna_tf32(bp[0]), b1 = rna_tf32(bp[4 * PBST]);
                #pragma unroll
                for (int mt = 0; mt < 4; mt++)
                    mma_tf32(acc[mt][nt], ar[mt], b0, b1);
            }
        }
    }
    __syncthreads();                             // smem reused as T below

    // Epilogue: +bias, transpose through smem, fp16 store to g_padh
    float* T = sm;                               // [128 px][132]
    #pragma unroll
    for (int mt = 0; mt < 4; mt++) {
        int o = ow * 64 + mt * 16 + g;
        float bl = __ldg(pb + o), bh = __ldg(pb + o + 8);
        #pragma unroll
        for (int nt = 0; nt < 4; nt++) {
            int n0 = pwv * 32 + nt * 8 + 2 * q;
            T[n0 * 132 + o]           = acc[mt][nt][0] + bl;
            T[(n0 + 1) * 132 + o]     = acc[mt][nt][1] + bl;
            T[n0 * 132 + o + 8]       = acc[mt][nt][2] + bh;
            T[(n0 + 1) * 132 + o + 8] = acc[mt][nt][3] + bh;
        }
    }
    __syncthreads();
    #pragma unroll
    for (int i = 0; i < 16; i++) {
        int idx = tid + i * 256;
        int row = idx >> 5, c4 = idx & 31;
        int px = pxbase + row, y = px >> 5, x = px & 31;
        float4 v = *reinterpret_cast<const float4*>(T + row * 132 + c4 * 4);
        __half2 h0 = __floats2half2_rn(v.x, v.y);
        __half2 h1 = __floats2half2_rn(v.z, v.w);
        uint2 u;
        u.x = *reinterpret_cast<uint32_t*>(&h0);
        u.y = *reinterpret_cast<uint32_t*>(&h1);
        *reinterpret_cast<uint2*>(
            g_padh + (((size_t)b * 34 + 1 + y) * 32 + x) * CDIM + c4 * 4) = u;
    }
}

// ===========================================================================
// Kernel 2: conv, fp16 m16n8k16, RESIDENT B window + streamed A.
// CTA: 128 o x 128 px (4 out rows), 256 thr, 8 warps (2o x 4px).
// B: 6 rows x 34 x(x-padded) x 128 c fp16, loaded ONCE; all 9 taps read it
//    via per-lane ldmatrix row addresses at (y+dy, x+dx).
// A: w_h tap halves streamed, 18 stages (9 taps x 2 k64), 3-ring, 1 sync.
// ===========================================================================
#define CAH 72                                   // A smem row stride (halves)
#define CBH 136                                  // B smem (row,x) stride (halves)
#define B_RES (6 * 34 * CBH)                     // 27744 halves
#define A_STG (128 * CAH)                        // 9216 halves
#define CONV_SMEM ((B_RES + 3 * A_STG) * 2)      // 110784 B
#define NSTG 18

__global__ __launch_bounds__(256, 2) void conv_kernel(
    const float* __restrict__ qrep, float* __restrict__ out)
{
    extern __shared__ __half smh[];
    const int tid = threadIdx.x, lane = tid & 31, warp = tid >> 5;
    const int g = lane >> 2, q = lane & 3;
    const int ow = warp & 1, pwv = warp >> 1;
    const int ytile = blockIdx.x, b = blockIdx.y;
    const uint32_t sbase = smem_u32(smh);

    // ---- B: zero the two x-pad column slots, then load the 6x32 window
    #pragma unroll
    for (int i = tid; i < 6 * 2 * 16; i += 256) {
        int rr = i >> 5, rem = i & 31;
        int side = rem >> 4, u = rem & 15;
        int x = side ? 33 : 0;
        *reinterpret_cast<uint4*>(smh + (rr * 34 + x) * CBH + u * 8) =
            make_uint4(0, 0, 0, 0);
    }
    {
        const __half* bsrc = g_padh + ((size_t)b * 34 + ytile * 4) * 32 * CDIM;
        #pragma unroll
        for (int i = 0; i < 12; i++) {            // 3072 16B chunks / 256 thr
            int f = tid + i * 256;
            int k16 = f & 15, x = (f >> 4) & 31, rr = f >> 9;
            CP_ASYNC16(sbase + ((rr * 34 + x + 1) * CBH + k16 * 8) * 2,
                       bsrc + (rr * 32 + x) * CDIM + k16 * 8);
        }
        CP_COMMIT();                              // group: B window
    }

    const __half* wbase = w_h + (size_t)b * 9 * CDIM * CDIM;
    auto issueA = [&](int s) {
        const int tap = s >> 1, kc = s & 1;
        const uint32_t sa = sbase + (B_RES + (s % 3) * A_STG) * 2;
        const __half* wsrc = wbase + tap * (CDIM * CDIM) + kc * 64;
        #pragma unroll
        for (int i = 0; i < 4; i++) {             // A: 128 o x 64 k halves
            int f = tid + i * 256;
            int r = f >> 3, k16 = f & 7;
            CP_ASYNC16(sa + (r * CAH + k16 * 8) * 2, wsrc + r * CDIM + k16 * 8);
        }
        CP_COMMIT();
    };

    // ldmatrix per-lane geometry
    const int aRow = ((lane >> 3) & 1) * 8 + (lane & 7);
    const int aK   = (lane >> 4) * 8;
    const int m    = lane >> 3;
    const int bRow = (m >> 1) * 8 + (lane & 7);   // n row within 16-px group
    const int bK   = (m & 1) * 8;
    // Per-lane (rr, x) of this lane's B row for each ntp (loop-invariant)
    int rrB[2], xB[2];
    #pragma unroll
    for (int ntp = 0; ntp < 2; ntp++) {
        int px = pwv * 32 + ntp * 16 + bRow;
        rrB[ntp] = px >> 5;
        xB[ntp]  = px & 31;
    }

    float acc[4][4][4];
    #pragma unroll
    for (int mt = 0; mt < 4; mt++)
        #pragma unroll
        for (int nt = 0; nt < 4; nt++)
            #pragma unroll
            for (int k = 0; k < 4; k++) acc[mt][nt][k] = 0.f;

    issueA(0); issueA(1);

    for (int s = 0; s < NSTG; s++) {
        if (s + 1 < NSTG) CP_WAIT(1);             // B + A_s complete
        else              CP_WAIT(0);
        __syncthreads();
        if (s + 2 < NSTG) issueA(s + 2);

        const int tap = s >> 1, kc = s & 1;
        const int dy = tap / 3, dx = tap % 3;
        const uint32_t aBase = sbase + (B_RES + (s % 3) * A_STG) * 2;

        #pragma unroll
        for (int j = 0; j < 4; j++) {             // k16 step within k64
            uint32_t af[4][4], bf[2][4];
            #pragma unroll
            for (int mt = 0; mt < 4; mt++) {
                uint32_t addr = aBase +
                    ((ow * 64 + mt * 16 + aRow) * CAH + j * 16 + aK) * 2;
                LDSM_X4(af[mt][0], af[mt][1], af[mt][2], af[mt][3], addr);
            }
            #pragma unroll
            for (int ntp = 0; ntp < 2; ntp++) {
                uint32_t addr = sbase +
                    (((rrB[ntp] + dy) * 34 + xB[ntp] + dx) * CBH +
                     kc * 64 + j * 16 + bK) * 2;
                LDSM_X4(bf[ntp][0], bf[ntp][1], bf[ntp][2], bf[ntp][3], addr);
            }
            #pragma unroll
            for (int nt = 0; nt < 4; nt++) {
                uint32_t b0 = bf[nt >> 1][(nt & 1) * 2];
                uint32_t b1 = bf[nt >> 1][(nt & 1) * 2 + 1];
                #pragma unroll
                for (int mt = 0; mt < 4; mt++)
                    mma_f16(acc[mt][nt], af[mt], b0, b1);
            }
        }
    }

    // Epilogue: +per-sample bias, float2 stores
    const float* bsrc = qrep + (size_t)b * WDIM + WOFF;
    #pragma unroll
    for (int mt = 0; mt < 4; mt++) {
        int o  = ow * 64 + mt * 16 + g;
        float bl = __ldg(bsrc + o), bh = __ldg(bsrc + o + 8);
        #pragma unroll
        for (int nt = 0; nt < 4; nt++) {
            int px = ytile * 128 + pwv * 32 + nt * 8 + 2 * q;
            float2 v0 = make_float2(acc[mt][nt][0] + bl, acc[mt][nt][1] + bl);
            float2 v1 = make_float2(acc[mt][nt][2] + bh, acc[mt][nt][3] + bh);
            *reinterpret_cast<float2*>(out + ((size_t)b * CDIM + o)     * NPX + px) = v0;
            *reinterpret_cast<float2*>(out + ((size_t)b * CDIM + o + 8) * NPX + px) = v1;
        }
    }
}

// ===========================================================================
extern "C" void kernel_launch(void* const* d_in, const int* in_sizes, int n_in,
                              void* d_out, int out_size)
{
    const float* qrep = (const float*)d_in[0];   // (64, 147584)
    const float* lhs  = (const float*)d_in[1];   // (64, 128, 32, 32)
    const float* rhs  = (const float*)d_in[2];   // (64, 128, 32, 32)
    const float* pw   = (const float*)d_in[3];   // (128, 256)
    const float* pb   = (const float*)d_in[4];   // (128,)
    float* out = (float*)d_out;                  // (64, 128, 32, 32)

    static bool attr_done = false;
    if (!attr_done) {
        cudaFuncSetAttribute(wtrans_kernel,
            cudaFuncAttributeMaxDynamicSharedMemorySize, WT_SMEM);
        cudaFuncSetAttribute(proj_kernel,
            cudaFuncAttributeMaxDynamicSharedMemorySize, PROJ_SMEM);
        cudaFuncSetAttribute(conv_kernel,
            cudaFuncAttributeMaxDynamicSharedMemorySize, CONV_SMEM);
        attr_done = true;
    }

    wtrans_kernel<<<dim3(8, BB), 256, WT_SMEM>>>(qrep);
    proj_kernel<<<dim3(8, BB), 256, PROJ_SMEM>>>(lhs, rhs, pw, pb);
    conv_kernel<<<dim3(8, BB), 256, CONV_SMEM>>>(qrep, out);
}